// round 1
// baseline (speedup 1.0000x reference)
#include <cuda_runtime.h>
#include <mma.h>
#include <math.h>

using namespace nvcuda;

#define BB 4
#define ND 512
#define NT 512
#define DM 256
#define NH 8
#define DK 32
#define DH 128

// ---- scratch (static device globals; no runtime allocation) ----
__device__ float g_Q[BB*NH*ND*DK];        // [b,h,n,dk]
__device__ float g_K[BB*NH*NT*DK];        // [b,h,t,dk]
__device__ float g_V[BB*NH*NT*DK];        // [b,h,t,dk]
__device__ float g_attn[(size_t)BB*NH*ND*NT]; // [b,h,q,k]  33.5 MB
__device__ float g_ctx[BB*ND*DM];         // [b,n, h*32+dk]
__device__ float g_attout[BB*ND*DM];      // attended (pre-residual)
__device__ float g_xn[BB*ND*DM];          // LayerNorm output

// ============================================================
// Generic fp32 GEMM: C[2048,256] = X[2048,256] @ W[256,256]^T + bias
// src: 0 -> use Xarg, 1 -> use g_ctx
// dst: 0 -> g_Q ([b,h,n,dk] layout), 1 -> g_K, 2 -> g_V, 3 -> g_attout (row major)
// ============================================================
__global__ void gemm256(const float* __restrict__ Xarg,
                        const float* __restrict__ W,
                        const float* __restrict__ bias,
                        int src, int dst)
{
    const float* X = (src == 0) ? Xarg : g_ctx;
    __shared__ float Xs[16][65];   // [k][m]
    __shared__ float Ws[16][65];   // [k][n]
    int tid = threadIdx.x;
    int tx = tid & 15, ty = tid >> 4;            // 16x16 thread grid
    int m0 = blockIdx.y * 64, n0 = blockIdx.x * 64;

    float acc[4][4] = {};
    for (int k0 = 0; k0 < 256; k0 += 16) {
        #pragma unroll
        for (int r = 0; r < 4; r++) {
            int idx = tid + 256 * r;
            int kk = idx & 15, mm = idx >> 4;
            Xs[kk][mm] = X[(m0 + mm) * 256 + k0 + kk];
            Ws[kk][mm] = W[(n0 + mm) * 256 + k0 + kk];
        }
        __syncthreads();
        #pragma unroll
        for (int kk = 0; kk < 16; kk++) {
            float a[4], b[4];
            #pragma unroll
            for (int i = 0; i < 4; i++) { a[i] = Xs[kk][ty*4+i]; b[i] = Ws[kk][tx*4+i]; }
            #pragma unroll
            for (int i = 0; i < 4; i++)
                #pragma unroll
                for (int j = 0; j < 4; j++)
                    acc[i][j] += a[i] * b[j];
        }
        __syncthreads();
    }
    #pragma unroll
    for (int i = 0; i < 4; i++) {
        int m = m0 + ty*4 + i;
        #pragma unroll
        for (int j = 0; j < 4; j++) {
            int n = n0 + tx*4 + j;
            float v = acc[i][j] + bias[n];
            if (dst == 3) {
                g_attout[m * 256 + n] = v;
            } else {
                int b  = m >> 9;         // row / 512
                int nn = m & 511;
                int h  = n >> 5;
                int dk = n & 31;
                float* o = (dst == 0) ? g_Q : (dst == 1) ? g_K : g_V;
                o[((b * NH + h) * 512 + nn) * DK + dk] = v;
            }
        }
    }
}

// ============================================================
// scores + softmax: one warp per query row, 8 rows per block
// ============================================================
__global__ void attn_softmax_kernel()
{
    int b = blockIdx.z, h = blockIdx.y;
    int warp = threadIdx.x >> 5, lane = threadIdx.x & 31;
    int q = blockIdx.x * 8 + warp;
    int bh = b * NH + h;

    __shared__ float qs[8][32];
    qs[warp][lane] = g_Q[(bh * ND + q) * DK + lane];
    __syncwarp();

    const float* Kb = &g_K[bh * NT * DK];
    float s[16];
    #pragma unroll
    for (int i = 0; i < 16; i++) {
        int k = i * 32 + lane;
        const float* kr = Kb + k * DK;
        float acc = 0.f;
        #pragma unroll
        for (int d = 0; d < 32; d++) acc += qs[warp][d] * kr[d];
        s[i] = acc * 0.17677669529663689f;  // 1/sqrt(32)
    }
    float m = s[0];
    #pragma unroll
    for (int i = 1; i < 16; i++) m = fmaxf(m, s[i]);
    #pragma unroll
    for (int o = 16; o; o >>= 1) m = fmaxf(m, __shfl_xor_sync(0xffffffffu, m, o));
    float sum = 0.f;
    #pragma unroll
    for (int i = 0; i < 16; i++) { s[i] = expf(s[i] - m); sum += s[i]; }
    #pragma unroll
    for (int o = 16; o; o >>= 1) sum += __shfl_xor_sync(0xffffffffu, sum, o);
    float inv = 1.f / sum;
    float* arow = &g_attn[((size_t)bh * ND + q) * NT];
    #pragma unroll
    for (int i = 0; i < 16; i++) arow[i * 32 + lane] = s[i] * inv;
}

// ============================================================
// ctx = attn @ V  (per (b,h): [512,512] @ [512,32])
// block: (qtile 64, h, b), 256 threads
// ============================================================
__global__ void ctx_kernel()
{
    int b = blockIdx.z, h = blockIdx.y, q0 = blockIdx.x * 64;
    int bh = b * NH + h;
    __shared__ float As[64][65];
    __shared__ float Vs[64][32];
    int tid = threadIdx.x;
    int d = tid & 31, qg = tid >> 5;   // qg 0..7
    float acc[8] = {};

    for (int k0 = 0; k0 < NT; k0 += 64) {
        #pragma unroll
        for (int r = 0; r < 16; r++) {
            int idx = tid + 256 * r;
            int qi = idx >> 6, kk = idx & 63;
            As[qi][kk] = g_attn[((size_t)bh * ND + q0 + qi) * NT + k0 + kk];
        }
        #pragma unroll
        for (int r = 0; r < 8; r++) {
            int idx = tid + 256 * r;
            int kk = idx >> 5, dd = idx & 31;
            Vs[kk][dd] = g_V[(bh * NT + k0 + kk) * DK + dd];
        }
        __syncthreads();
        #pragma unroll
        for (int kk = 0; kk < 64; kk++) {
            float v = Vs[kk][d];
            #pragma unroll
            for (int j = 0; j < 8; j++) acc[j] += As[qg + 8*j][kk] * v;
        }
        __syncthreads();
    }
    #pragma unroll
    for (int j = 0; j < 8; j++) {
        int q = q0 + qg + 8*j;
        g_ctx[(b * ND + q) * DM + h * DK + d] = acc[j];
    }
}

// ============================================================
// residual + LayerNorm: one block per row (256 threads = D_MODEL)
// ============================================================
__global__ void ln_kernel(const float* __restrict__ det,
                          const float* __restrict__ ln_g,
                          const float* __restrict__ ln_b)
{
    int row = blockIdx.x, t = threadIdx.x;
    float x = det[row * 256 + t] + g_attout[row * 256 + t];
    float s1 = x, s2 = x * x;
    #pragma unroll
    for (int o = 16; o; o >>= 1) {
        s1 += __shfl_xor_sync(0xffffffffu, s1, o);
        s2 += __shfl_xor_sync(0xffffffffu, s2, o);
    }
    __shared__ float r1[8], r2[8];
    int w = t >> 5, l = t & 31;
    if (!l) { r1[w] = s1; r2[w] = s2; }
    __syncthreads();
    if (w == 0) {
        float a = (l < 8) ? r1[l] : 0.f;
        float c = (l < 8) ? r2[l] : 0.f;
        #pragma unroll
        for (int o = 4; o; o >>= 1) {
            a += __shfl_xor_sync(0xffffffffu, a, o);
            c += __shfl_xor_sync(0xffffffffu, c, o);
        }
        if (!l) { r1[0] = a; r2[0] = c; }
    }
    __syncthreads();
    float mu  = r1[0] * (1.f / 256.f);
    float var = r2[0] * (1.f / 256.f) - mu * mu;
    float xn = (x - mu) * rsqrtf(var + 1e-5f) * ln_g[t] + ln_b[t];
    g_xn[row * 256 + t] = xn;
}

// ============================================================
// Pairwise MLP: per block (b, n, t-tile of 128):
//   A[t,k] = tracks[b,t,k]*xn[b,n,k];  H = A @ W1^T (tf32 wmma)
//   out[t] = sigmoid( sum_h relu(H[t,h]+b1[h]) * w2[h] + b2 )
// ============================================================
#define LDA 40     // 32 + 8 pad  (multiple of 8)
#define LDH 132    // 128 + 4 pad (multiple of 4)
#define MLP_SMEM ((2 * 128 * LDA + 128 * LDH) * 4)

__global__ void mlp_kernel(const float* __restrict__ tracks,
                           const float* __restrict__ w1,
                           const float* __restrict__ b1,
                           const float* __restrict__ w2,
                           const float* __restrict__ b2,
                           float* __restrict__ out)
{
    extern __shared__ float sm[];
    float* As = sm;                      // [128][LDA]
    float* Bs = sm + 128 * LDA;          // [128][LDA]
    float* Hs = sm + 2 * 128 * LDA;      // [128][LDH]
    __shared__ float xns[256];
    __shared__ float b1s[128], w2s[128];

    int b = blockIdx.z;
    int n = blockIdx.y;
    int t0 = blockIdx.x * 128;
    int tid = threadIdx.x;

    xns[tid] = g_xn[(b * ND + n) * DM + tid];
    if (tid < 128) { b1s[tid] = b1[tid]; w2s[tid] = w2[tid]; }
    __syncthreads();

    int warp = tid >> 5, lane = tid & 31;
    int wt = (warp & 3) * 32;    // t offset of this warp's tiles
    int wh = (warp >> 2) * 64;   // h offset

    wmma::fragment<wmma::accumulator, 16, 16, 8, float> cf[2][4];
    #pragma unroll
    for (int i = 0; i < 2; i++)
        #pragma unroll
        for (int j = 0; j < 4; j++) wmma::fill_fragment(cf[i][j], 0.f);

    const float* trk = tracks + (b * NT + t0) * DM;
    int kk = tid & 31, trow = tid >> 5;

    for (int k0 = 0; k0 < 256; k0 += 32) {
        #pragma unroll
        for (int r = 0; r < 16; r++) {
            int ti = trow + r * 8;
            As[ti * LDA + kk] = trk[ti * 256 + k0 + kk] * xns[k0 + kk];
            Bs[ti * LDA + kk] = w1[ti * 256 + k0 + kk];
        }
        __syncthreads();
        #pragma unroll
        for (int ks = 0; ks < 32; ks += 8) {
            wmma::fragment<wmma::matrix_a, 16, 16, 8, wmma::precision::tf32, wmma::row_major> af[2];
            wmma::fragment<wmma::matrix_b, 16, 16, 8, wmma::precision::tf32, wmma::col_major> bf[4];
            #pragma unroll
            for (int i = 0; i < 2; i++) {
                wmma::load_matrix_sync(af[i], &As[(wt + 16*i) * LDA + ks], LDA);
                #pragma unroll
                for (int e = 0; e < af[i].num_elements; e++)
                    af[i].x[e] = wmma::__float_to_tf32(af[i].x[e]);
            }
            #pragma unroll
            for (int j = 0; j < 4; j++) {
                wmma::load_matrix_sync(bf[j], &Bs[(wh + 16*j) * LDA + ks], LDA);
                #pragma unroll
                for (int e = 0; e < bf[j].num_elements; e++)
                    bf[j].x[e] = wmma::__float_to_tf32(bf[j].x[e]);
            }
            #pragma unroll
            for (int i = 0; i < 2; i++)
                #pragma unroll
                for (int j = 0; j < 4; j++)
                    wmma::mma_sync(cf[i][j], af[i], bf[j], cf[i][j]);
        }
        __syncthreads();
    }

    // epilogue: H -> smem, relu, dot with w2, sigmoid
    #pragma unroll
    for (int i = 0; i < 2; i++)
        #pragma unroll
        for (int j = 0; j < 4; j++)
            wmma::store_matrix_sync(&Hs[(wt + 16*i) * LDH + wh + 16*j], cf[i][j],
                                    LDH, wmma::mem_row_major);
    __syncthreads();

    float bias2 = b2[0];
    #pragma unroll
    for (int r = 0; r < 16; r++) {
        int t = warp * 16 + r;
        float acc = 0.f;
        #pragma unroll
        for (int h0 = 0; h0 < 128; h0 += 32) {
            int h = h0 + lane;
            float v = Hs[t * LDH + h] + b1s[h];
            acc += fmaxf(v, 0.f) * w2s[h];
        }
        #pragma unroll
        for (int o = 16; o; o >>= 1) acc += __shfl_xor_sync(0xffffffffu, acc, o);
        if (lane == 0) {
            float logit = acc + bias2;
            out[((size_t)(b * ND + n)) * NT + t0 + t] = 1.f / (1.f + expf(-logit));
        }
    }
}

// ============================================================
extern "C" void kernel_launch(void* const* d_in, const int* in_sizes, int n_in,
                              void* d_out, int out_size)
{
    const float* det  = (const float*)d_in[0];
    const float* trk  = (const float*)d_in[1];
    const float* w_q  = (const float*)d_in[2];
    const float* b_q  = (const float*)d_in[3];
    const float* w_k  = (const float*)d_in[4];
    const float* b_k  = (const float*)d_in[5];
    const float* w_v  = (const float*)d_in[6];
    const float* b_v  = (const float*)d_in[7];
    const float* w_o  = (const float*)d_in[8];
    const float* b_o  = (const float*)d_in[9];
    const float* ln_g = (const float*)d_in[10];
    const float* ln_b = (const float*)d_in[11];
    const float* w1   = (const float*)d_in[12];
    const float* b1   = (const float*)d_in[13];
    const float* w2   = (const float*)d_in[14];
    const float* b2   = (const float*)d_in[15];
    float* out = (float*)d_out;

    cudaFuncSetAttribute(mlp_kernel,
                         cudaFuncAttributeMaxDynamicSharedMemorySize, MLP_SMEM);

    dim3 gg(4, 32);
    gemm256<<<gg, 256>>>(det, w_q, b_q, 0, 0);   // Q
    gemm256<<<gg, 256>>>(trk, w_k, b_k, 0, 1);   // K
    gemm256<<<gg, 256>>>(trk, w_v, b_v, 0, 2);   // V
    attn_softmax_kernel<<<dim3(64, NH, BB), 256>>>();
    ctx_kernel<<<dim3(8, NH, BB), 256>>>();
    gemm256<<<gg, 256>>>(nullptr, w_o, b_o, 1, 3);   // attended (X = g_ctx)
    ln_kernel<<<BB * ND, 256>>>(det, ln_g, ln_b);
    mlp_kernel<<<dim3(4, ND, BB), 256, MLP_SMEM>>>(trk, w1, b1, w2, b2, out);
}

// round 2
// speedup vs baseline: 1.6817x; 1.6817x over previous
#include <cuda_runtime.h>
#include <mma.h>
#include <math.h>

using namespace nvcuda;

#define BB 4
#define ND 512
#define NT 512
#define DM 256
#define NH 8
#define DK 32
#define DH 128

// ---- scratch (static device globals; no runtime allocation) ----
__device__ float g_Q[BB*NH*ND*DK];        // [b,h,n,dk]
__device__ float g_K[BB*NH*NT*DK];        // [b,h,t,dk]
__device__ float g_V[BB*NH*NT*DK];        // [b,h,t,dk]
__device__ float g_ctx[BB*ND*DM];         // [b,n, h*32+dk]
__device__ float g_attout[BB*ND*DM];      // attended (pre-residual)
__device__ float g_xn[BB*ND*DM];          // LayerNorm output

// ============================================================
// QKV GEMM (merged): C[2048,256] = X @ W^T + bias, z selects Q/K/V
// output layout [b,h,n,dk]
// ============================================================
__global__ void qkv_gemm(const float* __restrict__ det,
                         const float* __restrict__ trk,
                         const float* __restrict__ w_q, const float* __restrict__ b_q,
                         const float* __restrict__ w_k, const float* __restrict__ b_k,
                         const float* __restrict__ w_v, const float* __restrict__ b_v)
{
    int z = blockIdx.z;
    const float* X    = (z == 0) ? det : trk;
    const float* W    = (z == 0) ? w_q : (z == 1) ? w_k : w_v;
    const float* bias = (z == 0) ? b_q : (z == 1) ? b_k : b_v;
    float* O          = (z == 0) ? g_Q : (z == 1) ? g_K : g_V;

    __shared__ float Xs[16][65];
    __shared__ float Ws[16][65];
    int tid = threadIdx.x;
    int tx = tid & 15, ty = tid >> 4;
    int m0 = blockIdx.y * 64, n0 = blockIdx.x * 64;

    float acc[4][4] = {};
    for (int k0 = 0; k0 < 256; k0 += 16) {
        #pragma unroll
        for (int r = 0; r < 4; r++) {
            int idx = tid + 256 * r;
            int kk = idx & 15, mm = idx >> 4;
            Xs[kk][mm] = X[(m0 + mm) * 256 + k0 + kk];
            Ws[kk][mm] = W[(n0 + mm) * 256 + k0 + kk];
        }
        __syncthreads();
        #pragma unroll
        for (int kk = 0; kk < 16; kk++) {
            float a[4], b[4];
            #pragma unroll
            for (int i = 0; i < 4; i++) { a[i] = Xs[kk][ty*4+i]; b[i] = Ws[kk][tx*4+i]; }
            #pragma unroll
            for (int i = 0; i < 4; i++)
                #pragma unroll
                for (int j = 0; j < 4; j++)
                    acc[i][j] += a[i] * b[j];
        }
        __syncthreads();
    }
    #pragma unroll
    for (int i = 0; i < 4; i++) {
        int m = m0 + ty*4 + i;
        int b = m >> 9, nn = m & 511;
        #pragma unroll
        for (int j = 0; j < 4; j++) {
            int n = n0 + tx*4 + j;
            int h = n >> 5, dk = n & 31;
            O[((b * NH + h) * 512 + nn) * DK + dk] = acc[i][j] + bias[n];
        }
    }
}

// ============================================================
// output projection GEMM: g_attout = g_ctx @ w_o^T + b_o
// ============================================================
__global__ void gemm_o(const float* __restrict__ W, const float* __restrict__ bias)
{
    const float* X = g_ctx;
    __shared__ float Xs[16][65];
    __shared__ float Ws[16][65];
    int tid = threadIdx.x;
    int tx = tid & 15, ty = tid >> 4;
    int m0 = blockIdx.y * 64, n0 = blockIdx.x * 64;

    float acc[4][4] = {};
    for (int k0 = 0; k0 < 256; k0 += 16) {
        #pragma unroll
        for (int r = 0; r < 4; r++) {
            int idx = tid + 256 * r;
            int kk = idx & 15, mm = idx >> 4;
            Xs[kk][mm] = X[(m0 + mm) * 256 + k0 + kk];
            Ws[kk][mm] = W[(n0 + mm) * 256 + k0 + kk];
        }
        __syncthreads();
        #pragma unroll
        for (int kk = 0; kk < 16; kk++) {
            float a[4], b[4];
            #pragma unroll
            for (int i = 0; i < 4; i++) { a[i] = Xs[kk][ty*4+i]; b[i] = Ws[kk][tx*4+i]; }
            #pragma unroll
            for (int i = 0; i < 4; i++)
                #pragma unroll
                for (int j = 0; j < 4; j++)
                    acc[i][j] += a[i] * b[j];
        }
        __syncthreads();
    }
    #pragma unroll
    for (int i = 0; i < 4; i++) {
        int m = m0 + ty*4 + i;
        #pragma unroll
        for (int j = 0; j < 4; j++) {
            int n = n0 + tx*4 + j;
            g_attout[m * 256 + n] = acc[i][j] + bias[n];
        }
    }
}

// ============================================================
// Fused attention: per block (qtile 32, h, b)
//   scores S[32,512] = Q K^T * scale (smem-tiled, coalesced loads)
//   softmax in smem (warp-local rows)
//   ctx[32,32] = S @ V, written to g_ctx
// ============================================================
#define ATT_SMEM ((32*512 + 64*33 + 32*33) * 4)

__global__ void fused_attn()
{
    extern __shared__ float sm[];
    float* S  = sm;                        // [32][512]
    float* KV = sm + 32*512;               // [64][33]  (K tiles, then V tiles)
    float* Qs = sm + 32*512 + 64*33;       // [32][33]

    int b = blockIdx.z, h = blockIdx.y, q0 = blockIdx.x * 32;
    int bh = b * NH + h;
    int tid = threadIdx.x;
    int warp = tid >> 5, lane = tid & 31;

    // load Q tile [32][32]
    #pragma unroll
    for (int r = 0; r < 4; r++) {
        int idx = tid + 256 * r;
        int row = idx >> 5, d = idx & 31;
        Qs[row * 33 + d] = g_Q[(bh * ND + q0 + row) * DK + d];
    }

    const float scale = 0.17677669529663689f;  // 1/sqrt(32)

    // ---- scores ----
    for (int k0 = 0; k0 < NT; k0 += 64) {
        #pragma unroll
        for (int r = 0; r < 8; r++) {
            int idx = tid + 256 * r;
            int kk = idx >> 5, d = idx & 31;
            KV[kk * 33 + d] = g_K[(bh * NT + k0 + kk) * DK + d];
        }
        __syncthreads();
        float acc[4][2] = {};
        #pragma unroll
        for (int d = 0; d < 32; d++) {
            float kv0 = KV[lane * 33 + d];
            float kv1 = KV[(lane + 32) * 33 + d];
            #pragma unroll
            for (int qi = 0; qi < 4; qi++) {
                float qv = Qs[(warp * 4 + qi) * 33 + d];
                acc[qi][0] += qv * kv0;
                acc[qi][1] += qv * kv1;
            }
        }
        #pragma unroll
        for (int qi = 0; qi < 4; qi++) {
            S[(warp * 4 + qi) * 512 + k0 + lane]      = acc[qi][0] * scale;
            S[(warp * 4 + qi) * 512 + k0 + 32 + lane] = acc[qi][1] * scale;
        }
        __syncthreads();
    }

    // ---- softmax (warp-local rows; no cross-warp deps) ----
    #pragma unroll
    for (int qi = 0; qi < 4; qi++) {
        float* row = &S[(warp * 4 + qi) * 512];
        float v[16];
        float m = -1e30f;
        #pragma unroll
        for (int i = 0; i < 16; i++) { v[i] = row[i * 32 + lane]; m = fmaxf(m, v[i]); }
        #pragma unroll
        for (int o = 16; o; o >>= 1) m = fmaxf(m, __shfl_xor_sync(0xffffffffu, m, o));
        float sum = 0.f;
        #pragma unroll
        for (int i = 0; i < 16; i++) { v[i] = __expf(v[i] - m); sum += v[i]; }
        #pragma unroll
        for (int o = 16; o; o >>= 1) sum += __shfl_xor_sync(0xffffffffu, sum, o);
        float inv = 1.f / sum;
        #pragma unroll
        for (int i = 0; i < 16; i++) row[i * 32 + lane] = v[i] * inv;
    }

    // ---- ctx = S @ V ----
    float cacc[4] = {};
    for (int k0 = 0; k0 < NT; k0 += 64) {
        __syncthreads();
        #pragma unroll
        for (int r = 0; r < 8; r++) {
            int idx = tid + 256 * r;
            int kk = idx >> 5, d = idx & 31;
            KV[kk * 33 + d] = g_V[(bh * NT + k0 + kk) * DK + d];
        }
        __syncthreads();
        #pragma unroll
        for (int kk = 0; kk < 64; kk++) {
            float vv = KV[kk * 33 + lane];
            #pragma unroll
            for (int qi = 0; qi < 4; qi++)
                cacc[qi] += S[(warp * 4 + qi) * 512 + k0 + kk] * vv;
        }
    }
    #pragma unroll
    for (int qi = 0; qi < 4; qi++) {
        int q = q0 + warp * 4 + qi;
        g_ctx[(b * ND + q) * DM + h * DK + lane] = cacc[qi];
    }
}

// ============================================================
// residual + LayerNorm: one block per row (256 threads = D_MODEL)
// ============================================================
__global__ void ln_kernel(const float* __restrict__ det,
                          const float* __restrict__ ln_g,
                          const float* __restrict__ ln_b)
{
    int row = blockIdx.x, t = threadIdx.x;
    float x = det[row * 256 + t] + g_attout[row * 256 + t];
    float s1 = x, s2 = x * x;
    #pragma unroll
    for (int o = 16; o; o >>= 1) {
        s1 += __shfl_xor_sync(0xffffffffu, s1, o);
        s2 += __shfl_xor_sync(0xffffffffu, s2, o);
    }
    __shared__ float r1[8], r2[8];
    int w = t >> 5, l = t & 31;
    if (!l) { r1[w] = s1; r2[w] = s2; }
    __syncthreads();
    if (w == 0) {
        float a = (l < 8) ? r1[l] : 0.f;
        float c = (l < 8) ? r2[l] : 0.f;
        #pragma unroll
        for (int o = 4; o; o >>= 1) {
            a += __shfl_xor_sync(0xffffffffu, a, o);
            c += __shfl_xor_sync(0xffffffffu, c, o);
        }
        if (!l) { r1[0] = a; r2[0] = c; }
    }
    __syncthreads();
    float mu  = r1[0] * (1.f / 256.f);
    float var = r2[0] * (1.f / 256.f) - mu * mu;
    float xn = (x - mu) * rsqrtf(var + 1e-5f) * ln_g[t] + ln_b[t];
    g_xn[row * 256 + t] = xn;
}

// ============================================================
// Pairwise MLP: per block (b, n, t-tile of 128):
//   A[t,k] = tracks[b,t,k]*xn[b,n,k];  H = A @ W1^T (tf32 wmma)
//   out[t] = sigmoid( sum_h relu(H[t,h]+b1[h]) * w2[h] + b2 )
// smem tiles staged pre-converted to tf32.
// ============================================================
#define LDA 40     // 32 + 8 pad  (multiple of 8)
#define LDH 132    // 128 + 4 pad (multiple of 4)
#define MLP_SMEM ((2 * 128 * LDA + 128 * LDH) * 4)

__global__ void mlp_kernel(const float* __restrict__ tracks,
                           const float* __restrict__ w1,
                           const float* __restrict__ b1,
                           const float* __restrict__ w2,
                           const float* __restrict__ b2,
                           float* __restrict__ out)
{
    extern __shared__ float sm[];
    float* As = sm;                      // [128][LDA]
    float* Bs = sm + 128 * LDA;          // [128][LDA]
    float* Hs = sm + 2 * 128 * LDA;      // [128][LDH]
    __shared__ float xns[256];
    __shared__ float b1s[128], w2s[128];

    int b = blockIdx.z;
    int n = blockIdx.y;
    int t0 = blockIdx.x * 128;
    int tid = threadIdx.x;

    xns[tid] = g_xn[(b * ND + n) * DM + tid];
    if (tid < 128) { b1s[tid] = b1[tid]; w2s[tid] = w2[tid]; }
    __syncthreads();

    int warp = tid >> 5, lane = tid & 31;
    int wt = (warp & 3) * 32;    // t offset of this warp's tiles
    int wh = (warp >> 2) * 64;   // h offset

    wmma::fragment<wmma::accumulator, 16, 16, 8, float> cf[2][4];
    #pragma unroll
    for (int i = 0; i < 2; i++)
        #pragma unroll
        for (int j = 0; j < 4; j++) wmma::fill_fragment(cf[i][j], 0.f);

    const float* trk = tracks + (b * NT + t0) * DM;
    int kk = tid & 31, trow = tid >> 5;

    for (int k0 = 0; k0 < 256; k0 += 32) {
        #pragma unroll
        for (int r = 0; r < 16; r++) {
            int ti = trow + r * 8;
            As[ti * LDA + kk] = wmma::__float_to_tf32(trk[ti * 256 + k0 + kk] * xns[k0 + kk]);
            Bs[ti * LDA + kk] = wmma::__float_to_tf32(w1[ti * 256 + k0 + kk]);
        }
        __syncthreads();
        #pragma unroll
        for (int ks = 0; ks < 32; ks += 8) {
            wmma::fragment<wmma::matrix_a, 16, 16, 8, wmma::precision::tf32, wmma::row_major> af[2];
            wmma::fragment<wmma::matrix_b, 16, 16, 8, wmma::precision::tf32, wmma::col_major> bf[4];
            #pragma unroll
            for (int i = 0; i < 2; i++)
                wmma::load_matrix_sync(af[i], &As[(wt + 16*i) * LDA + ks], LDA);
            #pragma unroll
            for (int j = 0; j < 4; j++)
                wmma::load_matrix_sync(bf[j], &Bs[(wh + 16*j) * LDA + ks], LDA);
            #pragma unroll
            for (int i = 0; i < 2; i++)
                #pragma unroll
                for (int j = 0; j < 4; j++)
                    wmma::mma_sync(cf[i][j], af[i], bf[j], cf[i][j]);
        }
        __syncthreads();
    }

    // epilogue: H -> smem, relu, dot with w2, sigmoid
    #pragma unroll
    for (int i = 0; i < 2; i++)
        #pragma unroll
        for (int j = 0; j < 4; j++)
            wmma::store_matrix_sync(&Hs[(wt + 16*i) * LDH + wh + 16*j], cf[i][j],
                                    LDH, wmma::mem_row_major);
    __syncthreads();

    float bias2 = b2[0];
    #pragma unroll
    for (int r = 0; r < 16; r++) {
        int t = warp * 16 + r;
        float acc = 0.f;
        #pragma unroll
        for (int h0 = 0; h0 < 128; h0 += 32) {
            int h = h0 + lane;
            float v = Hs[t * LDH + h] + b1s[h];
            acc += fmaxf(v, 0.f) * w2s[h];
        }
        #pragma unroll
        for (int o = 16; o; o >>= 1) acc += __shfl_xor_sync(0xffffffffu, acc, o);
        if (lane == 0) {
            float logit = acc + bias2;
            out[((size_t)(b * ND + n)) * NT + t0 + t] = 1.f / (1.f + __expf(-logit));
        }
    }
}

// ============================================================
extern "C" void kernel_launch(void* const* d_in, const int* in_sizes, int n_in,
                              void* d_out, int out_size)
{
    const float* det  = (const float*)d_in[0];
    const float* trk  = (const float*)d_in[1];
    const float* w_q  = (const float*)d_in[2];
    const float* b_q  = (const float*)d_in[3];
    const float* w_k  = (const float*)d_in[4];
    const float* b_k  = (const float*)d_in[5];
    const float* w_v  = (const float*)d_in[6];
    const float* b_v  = (const float*)d_in[7];
    const float* w_o  = (const float*)d_in[8];
    const float* b_o  = (const float*)d_in[9];
    const float* ln_g = (const float*)d_in[10];
    const float* ln_b = (const float*)d_in[11];
    const float* w1   = (const float*)d_in[12];
    const float* b1   = (const float*)d_in[13];
    const float* w2   = (const float*)d_in[14];
    const float* b2   = (const float*)d_in[15];
    float* out = (float*)d_out;

    cudaFuncSetAttribute(mlp_kernel,
                         cudaFuncAttributeMaxDynamicSharedMemorySize, MLP_SMEM);
    cudaFuncSetAttribute(fused_attn,
                         cudaFuncAttributeMaxDynamicSharedMemorySize, ATT_SMEM);

    qkv_gemm<<<dim3(4, 32, 3), 256>>>(det, trk, w_q, b_q, w_k, b_k, w_v, b_v);
    fused_attn<<<dim3(16, NH, BB), 256, ATT_SMEM>>>();
    gemm_o<<<dim3(4, 32), 256>>>(w_o, b_o);
    ln_kernel<<<BB * ND, 256>>>(det, ln_g, ln_b);
    mlp_kernel<<<dim3(4, ND, BB), 256, MLP_SMEM>>>(trk, w1, b1, w2, b2, out);
}